// round 12
// baseline (speedup 1.0000x reference)
#include <cuda_runtime.h>
#include <cstdint>

// ---------------- problem constants (fixed by setup_inputs) ----------------
#define B_      2
#define NQ_     20000
#define MQ_     (B_*NQ_)          // 40000
#define LIN_    45109
#define MV_     (B_*LIN_)         // 90218
#define DM_     64
#define HEADS_  8
#define DH_     8
#define LEVELS_ 5
#define POINTS_ 4
#define EPS_    1e-5f

__device__ __constant__ int c_W[5] = {184, 92, 46, 23, 12};
__device__ __constant__ int c_H[5] = {184, 92, 46, 23, 12};
__device__ __constant__ int c_S[5] = {0, 33856, 42320, 44436, 44965};

// ---------------- scratch (device globals; no runtime allocation) ----------
__device__ float g_value [(size_t)MV_ * 64];     // 23.1 MB
__device__ float g_off   [(size_t)MQ_ * 320];    // 51.2 MB
__device__ float g_logits[(size_t)MQ_ * 160];    // 25.6 MB
__device__ float g_attn  [(size_t)MQ_ * 64];     // 10.2 MB
__device__ float g_x     [(size_t)MQ_ * 64];     // 10.2 MB
__device__ float g_W1T   [1024 * 64];            // W1 transposed [hid][k], tf32-rounded
__device__ float g_W2T   [64 * 1024];            // W2 transposed [col][k], tf32-rounded

// ---------------- packed fp32x2 helpers ------------------------------------
typedef unsigned long long u64;

__device__ __forceinline__ void fma2(u64 &d, u64 a, u64 b) {
    asm("fma.rn.f32x2 %0, %1, %2, %0;" : "+l"(d) : "l"(a), "l"(b));
}
__device__ __forceinline__ u64 bcast2(float a) {
    u64 r; asm("mov.b64 %0, {%1, %1};" : "=l"(r) : "f"(a)); return r;
}
__device__ __forceinline__ float2 unpack2(u64 v) {
    float2 f; asm("mov.b64 {%0, %1}, %2;" : "=f"(f.x), "=f"(f.y) : "l"(v)); return f;
}
__device__ __forceinline__ uint32_t f2tf32(float f) {
    uint32_t r; asm("cvt.rna.tf32.f32 %0, %1;" : "=r"(r) : "f"(f)); return r;
}

// m16n8k8 tf32 mma (sm_80+ feature; compiles at compute_103, runs on HMMA pipe)
__device__ __forceinline__ void mma_tf32(float c[4], const uint32_t a[4],
                                         uint32_t b0, uint32_t b1) {
    asm("mma.sync.aligned.m16n8k8.row.col.f32.tf32.tf32.f32 "
        "{%0,%1,%2,%3}, {%4,%5,%6,%7}, {%8,%9}, {%0,%1,%2,%3};"
        : "+f"(c[0]), "+f"(c[1]), "+f"(c[2]), "+f"(c[3])
        : "r"(a[0]), "r"(a[1]), "r"(a[2]), "r"(a[3]), "r"(b0), "r"(b1));
}

// ======================================================================
// One-shot transpose of W1/W2 into k-contiguous, tf32-rounded layouts.
// ======================================================================
__global__ __launch_bounds__(256)
void transpose_w_kernel(const float* __restrict__ W1, const float* __restrict__ W2)
{
    int t = blockIdx.x * 256 + threadIdx.x;
    if (t < 65536) {
        int k1 = t >> 10, n1 = t & 1023;   // W1[k][n]
        g_W1T[(size_t)n1 * 64 + k1] = __uint_as_float(f2tf32(W1[t]));
        int k2 = t >> 6, n2 = t & 63;      // W2[k][n]
        g_W2T[(size_t)n2 * 1024 + k2] = __uint_as_float(f2tf32(W2[t]));
    }
}

// ======================================================================
// Generic K=64 GEMM (fp32 FFMA2) for value/offset/logit projections.
// ======================================================================
template <int N>
__global__ __launch_bounds__(256)
void gemm64_kernel(const float* __restrict__ A1, const float* __restrict__ A2,
                   const float* __restrict__ W,  const float* __restrict__ bias,
                   float* __restrict__ C, int M)
{
    __shared__ float As[64 * 65];
    __shared__ float Ws[64 * 64];

    const int tid = threadIdx.x;
    const int m0  = blockIdx.x * 64;
    const int n0  = blockIdx.y * 64;

    #pragma unroll
    for (int i = 0; i < 4; i++) {
        int f   = tid + 256 * i;
        int row = f >> 4;
        int kc  = (f & 15) * 4;
        float4 v = make_float4(0.f, 0.f, 0.f, 0.f);
        if (m0 + row < M) {
            v = *(const float4*)&A1[(size_t)(m0 + row) * 64 + kc];
            if (A2) {
                float4 u = *(const float4*)&A2[(size_t)(m0 + row) * 64 + kc];
                v.x += u.x; v.y += u.y; v.z += u.z; v.w += u.w;
            }
        }
        As[(kc + 0) * 65 + row] = v.x;
        As[(kc + 1) * 65 + row] = v.y;
        As[(kc + 2) * 65 + row] = v.z;
        As[(kc + 3) * 65 + row] = v.w;
    }
    #pragma unroll
    for (int i = 0; i < 4; i++) {
        int f  = tid + 256 * i;
        int k  = f >> 4;
        int c4 = (f & 15) * 4;
        int col = n0 + c4;
        float4 v = make_float4(0.f, 0.f, 0.f, 0.f);
        if (col + 3 < N) {
            v = *(const float4*)&W[(size_t)k * N + col];
        } else {
            float t[4] = {0.f, 0.f, 0.f, 0.f};
            #pragma unroll
            for (int j = 0; j < 4; j++)
                if (col + j < N) t[j] = W[(size_t)k * N + col + j];
            v = make_float4(t[0], t[1], t[2], t[3]);
        }
        *(float4*)&Ws[k * 64 + c4] = v;
    }
    __syncthreads();

    const int tx = tid & 15;
    const int ty = tid >> 4;

    u64 acc[4][2];
    #pragma unroll
    for (int i = 0; i < 4; i++) { acc[i][0] = 0ull; acc[i][1] = 0ull; }

    #pragma unroll 8
    for (int k = 0; k < 64; k++) {
        ulonglong2 bv = *(const ulonglong2*)&Ws[k * 64 + tx * 4];
        #pragma unroll
        for (int i = 0; i < 4; i++) {
            u64 ap = bcast2(As[k * 65 + ty + 16 * i]);
            fma2(acc[i][0], ap, bv.x);
            fma2(acc[i][1], ap, bv.y);
        }
    }

    #pragma unroll
    for (int i = 0; i < 4; i++) {
        int row = m0 + ty + 16 * i;
        if (row >= M) continue;
        int col = n0 + tx * 4;
        float2 lo = unpack2(acc[i][0]);
        float2 hi = unpack2(acc[i][1]);
        float r[4] = {lo.x, lo.y, hi.x, hi.y};
        #pragma unroll
        for (int j = 0; j < 4; j++)
            if (col + j < N)
                C[(size_t)row * N + col + j] = r[j] + bias[col + j];
    }
}

// ======================================================================
// Deformable sampling: 2 warps per query (16B per lane, paired lanes
// share a 128B line).
// ======================================================================
__global__ __launch_bounds__(256)
void sample_kernel(const float* __restrict__ ref)
{
    const int gw = (blockIdx.x * 256 + threadIdx.x) >> 5;
    const int q  = gw >> 1;
    const int sub  = gw & 1;
    const int lane = threadIdx.x & 31;
    const int idx  = lane >> 1;
    const int half = lane & 1;
    const int h = sub * 4 + (idx >> 2);
    const int p = idx & 3;
    const int b = q / NQ_;

    const float* vb = g_value + (size_t)b * LIN_ * 64;
    const float rx = ref[q * 2 + 0];
    const float ry = ref[q * 2 + 1];

    const float* lg = g_logits + (size_t)q * 160 + h * 20;
    float m = -1e30f;
    #pragma unroll
    for (int i = 0; i < 20; i++) m = fmaxf(m, lg[i]);
    float s = 0.f, w5[5];
    #pragma unroll
    for (int i = 0; i < 20; i++) {
        float e = __expf(lg[i] - m);
        s += e;
        if ((i & 3) == p) w5[i >> 2] = e;
    }
    const float inv = 1.f / s;

    float acc[4] = {0.f, 0.f, 0.f, 0.f};
    const float* offq = g_off + (size_t)q * 320 + (h * 20 + p) * 2;

    #pragma unroll
    for (int l = 0; l < LEVELS_; l++) {
        const int   Wl = c_W[l], Hl = c_H[l], st = c_S[l];
        const float offx = offq[l * 8 + 0];
        const float offy = offq[l * 8 + 1];
        const float x = rx * (float)Wl + offx - 0.5f;
        const float y = ry * (float)Hl + offy - 0.5f;
        const float xf = floorf(x), yf = floorf(y);
        const float wx = x - xf, wy = y - yf;
        const int x0 = (int)xf, y0 = (int)yf;
        const float wt = w5[l] * inv;
        #pragma unroll
        for (int dy = 0; dy < 2; dy++) {
            #pragma unroll
            for (int dx = 0; dx < 2; dx++) {
                const int xc = x0 + dx, yc = y0 + dy;
                if (xc >= 0 && xc < Wl && yc >= 0 && yc < Hl) {
                    const float cw = (dx ? wx : 1.f - wx) * (dy ? wy : 1.f - wy) * wt;
                    const float4 v = *(const float4*)
                        (vb + ((size_t)(st + yc * Wl + xc) * 64 + h * 8 + half * 4));
                    acc[0] += cw * v.x; acc[1] += cw * v.y;
                    acc[2] += cw * v.z; acc[3] += cw * v.w;
                }
            }
        }
    }
    #pragma unroll
    for (int d = 0; d < 4; d++) {
        float v = acc[d];
        v += __shfl_xor_sync(0xffffffffu, v, 2);
        v += __shfl_xor_sync(0xffffffffu, v, 4);
        acc[d] = v;
    }
    if (p == 0) {
        *(float4*)&g_attn[(size_t)q * 64 + h * 8 + half * 4] =
            make_float4(acc[0], acc[1], acc[2], acc[3]);
    }
}

// ======================================================================
// attn_out @ Wout + bout, residual with q_feat, LayerNorm1.  Warp/query.
// ======================================================================
__global__ __launch_bounds__(256)
void proj_ln1_kernel(const float* __restrict__ qfeat,
                     const float* __restrict__ Wout, const float* __restrict__ bout,
                     const float* __restrict__ g1,   const float* __restrict__ b1)
{
    __shared__ float Ws[64 * 64];
    const int tid = threadIdx.x;
    #pragma unroll
    for (int i = tid * 4; i < 4096; i += 1024)
        *(float4*)&Ws[i] = *(const float4*)&Wout[i];
    __syncthreads();

    const int q = blockIdx.x * 8 + (tid >> 5);
    const int lane = tid & 31;

    const float a0 = g_attn[(size_t)q * 64 + lane];
    const float a1 = g_attn[(size_t)q * 64 + lane + 32];
    float acc0 = 0.f, acc1 = 0.f;
    #pragma unroll 8
    for (int k = 0; k < 32; k++) {
        float a = __shfl_sync(0xffffffffu, a0, k);
        acc0 += a * Ws[k * 64 + lane];
        acc1 += a * Ws[k * 64 + lane + 32];
    }
    #pragma unroll 8
    for (int k = 0; k < 32; k++) {
        float a = __shfl_sync(0xffffffffu, a1, k);
        acc0 += a * Ws[(k + 32) * 64 + lane];
        acc1 += a * Ws[(k + 32) * 64 + lane + 32];
    }
    float r0 = qfeat[(size_t)q * 64 + lane]      + acc0 + bout[lane];
    float r1 = qfeat[(size_t)q * 64 + lane + 32] + acc1 + bout[lane + 32];

    float sum = r0 + r1;
    #pragma unroll
    for (int o = 16; o; o >>= 1) sum += __shfl_xor_sync(0xffffffffu, sum, o);
    const float mean = sum * (1.f / 64.f);
    float d0 = r0 - mean, d1 = r1 - mean;
    float vs = d0 * d0 + d1 * d1;
    #pragma unroll
    for (int o = 16; o; o >>= 1) vs += __shfl_xor_sync(0xffffffffu, vs, o);
    const float rs = rsqrtf(vs * (1.f / 64.f) + EPS_);

    g_x[(size_t)q * 64 + lane]      = d0 * rs * g1[lane]      + b1[lane];
    g_x[(size_t)q * 64 + lane + 32] = d1 * rs * g1[lane + 32] + b1[lane + 32];
}

// ======================================================================
// FFN (64 -> 1024 relu -> 64) + residual + LN2 via mma.sync tf32.
// CTA = 128 queries, 8 warps. Each warp owns one 16-row m-tile:
//   - X A-fragments live in registers for the whole kernel (no LDS for A)
//   - W1/W2 chunks staged in fragment-permuted uint2 layout (LDS.64, no
//     bank conflicts)
//   - H handed from GEMM1 C-frags to GEMM2 A-frags through a per-warp
//     XOR-swizzled smem slice (conflict-free, __syncwarp only)
//   - residual + LN2 fused on register-resident C2 fragments
// SMEM: Bs1 32KB | Bs2 32KB | Hfrag 64KB (aliases X staging) | bias 4KB
// ======================================================================
#define FFN_SMEM_BYTES (32768 + 32768 + 65536 + 4096)

__global__ __launch_bounds__(256, 1)
void ffn_mma_kernel(const float* __restrict__ bff1, const float* __restrict__ bff2,
                    const float* __restrict__ g2v,  const float* __restrict__ b2v,
                    float* __restrict__ out)
{
    extern __shared__ __align__(16) char smem[];
    uint2*    bs1 = (uint2*)smem;                    // [s=8][n=16][lane=32]
    uint2*    bs2 = (uint2*)(smem + 32768);          // [t=16][n=8][lane=32]
    uint32_t* hf  = (uint32_t*)(smem + 65536);       // 8 warps x 2048 words
    float*    xs  = (float*)(smem + 65536);          // alias: [128][68]
    float*    b1s = (float*)(smem + 131072);         // 1024

    const int tid  = threadIdx.x;
    const int w    = tid >> 5;
    const int lane = tid & 31;
    const int g    = lane >> 2;       // fragment group row
    const int t4   = lane & 3;        // fragment thread-in-group
    const int q0   = blockIdx.x * 128;
    uint32_t* hfw  = hf + w * 2048;

    // ---- stage x (fp32) + bias1 into smem ----
    #pragma unroll
    for (int it = tid; it < 2048; it += 256) {
        int row = it >> 4, c4 = (it & 15) * 4;
        float4 v = make_float4(0.f, 0.f, 0.f, 0.f);
        if (q0 + row < MQ_) v = *(const float4*)&g_x[(size_t)(q0 + row) * 64 + c4];
        *(float4*)&xs[row * 68 + c4] = v;
    }
    #pragma unroll
    for (int i = tid; i < 1024; i += 256) b1s[i] = bff1[i];
    __syncthreads();

    // ---- X A-fragments -> registers (kept for all 8 chunks) ----
    uint32_t a[8][4];
    #pragma unroll
    for (int s = 0; s < 8; s++) {
        a[s][0] = f2tf32(xs[(w * 16 + g)     * 68 + s * 8 + t4]);
        a[s][1] = f2tf32(xs[(w * 16 + g + 8) * 68 + s * 8 + t4]);
        a[s][2] = f2tf32(xs[(w * 16 + g)     * 68 + s * 8 + t4 + 4]);
        a[s][3] = f2tf32(xs[(w * 16 + g + 8) * 68 + s * 8 + t4 + 4]);
    }
    __syncthreads();   // xs dead; hfrag region free for scatter

    float c2[8][4];
    #pragma unroll
    for (int n = 0; n < 8; n++)
        #pragma unroll
        for (int j = 0; j < 4; j++) c2[n][j] = 0.f;

    const uint32_t* W1u = (const uint32_t*)g_W1T;
    const uint32_t* W2u = (const uint32_t*)g_W2T;

    const int cxz = (lane & 2);                 // comp base: 0 (x/y) or 2 (z/w)
    const int lcs = (4 * g + 2 * (lane & 1)) ^ ((lane & 2) ? 16 : 0);

    for (int ch = 0; ch < 8; ch++) {
        // ---- stage W1 chunk fragments: b0/b1 for (s, ntile, lane) ----
        #pragma unroll
        for (int it = tid; it < 4096; it += 256) {
            int ln = it & 31, n = (it >> 5) & 15, s = it >> 9;
            const uint32_t* src =
                &W1u[(size_t)(ch * 128 + n * 8 + (ln >> 2)) * 64 + s * 8 + (ln & 3)];
            bs1[it] = make_uint2(src[0], src[4]);
        }
        // ---- stage W2 chunk fragments: b0/b1 for (t, ntile, lane) ----
        #pragma unroll
        for (int it = tid; it < 4096; it += 256) {
            int ln = it & 31, n = (it >> 5) & 7, tt = it >> 8;
            const uint32_t* src =
                &W2u[(size_t)(n * 8 + (ln >> 2)) * 1024 + ch * 128 + tt * 8 + (ln & 3)];
            bs2[it] = make_uint2(src[0], src[4]);
        }
        __syncthreads();

        // ---- GEMM1: H[16q x 128hid] = X @ W1chunk ----
        float c1[16][4];
        #pragma unroll
        for (int n = 0; n < 16; n++)
            #pragma unroll
            for (int j = 0; j < 4; j++) c1[n][j] = 0.f;

        #pragma unroll
        for (int s = 0; s < 8; s++)
            #pragma unroll
            for (int n = 0; n < 16; n++) {
                uint2 b = bs1[(s * 16 + n) * 32 + lane];
                mma_tf32(c1[n], a[s], b.x, b.y);
            }

        // ---- bias + relu + tf32, scatter C-frags -> A-frag layout ----
        #pragma unroll
        for (int n = 0; n < 16; n++) {
            int co = ch * 128 + n * 8 + 2 * t4;
            float h0 = fmaxf(c1[n][0] + b1s[co],     0.f);
            float h1 = fmaxf(c1[n][1] + b1s[co + 1], 0.f);
            float h2 = fmaxf(c1[n][2] + b1s[co],     0.f);
            float h3 = fmaxf(c1[n][3] + b1s[co + 1], 0.f);
            *(uint2*)&hfw[(n * 4 + cxz)     * 32 + lcs] = make_uint2(f2tf32(h0), f2tf32(h1));
            *(uint2*)&hfw[(n * 4 + cxz + 1) * 32 + lcs] = make_uint2(f2tf32(h2), f2tf32(h3));
        }
        __syncwarp();

        // ---- GEMM2: Y[16q x 64] += H @ W2chunk ----
        #pragma unroll
        for (int tt = 0; tt < 16; tt++) {
            uint32_t af[4];
            af[0] = hfw[(tt * 4 + 0) * 32 + lane];
            af[1] = hfw[(tt * 4 + 1) * 32 + lane];
            af[2] = hfw[(tt * 4 + 2) * 32 + (lane ^ 16)];
            af[3] = hfw[(tt * 4 + 3) * 32 + (lane ^ 16)];
            #pragma unroll
            for (int n = 0; n < 8; n++) {
                uint2 b = bs2[(tt * 8 + n) * 32 + lane];
                mma_tf32(c2[n], af, b.x, b.y);
            }
        }
        __syncthreads();   // guard Bs reuse by next chunk
    }

    // ---- epilogue: residual + LN2 on C2 fragments ----
    const int qa = q0 + w * 16 + g;
    const int qb = qa + 8;
    const bool va = qa < MQ_, vb = qb < MQ_;

    float ra[16], rb[16];
    float suma = 0.f, sumb = 0.f;
    #pragma unroll
    for (int n = 0; n < 8; n++) {
        #pragma unroll
        for (int j = 0; j < 2; j++) {
            int col = n * 8 + 2 * t4 + j;
            float bf = bff2[col];
            float xa = va ? g_x[(size_t)qa * 64 + col] : 0.f;
            float xb = vb ? g_x[(size_t)qb * 64 + col] : 0.f;
            ra[n * 2 + j] = c2[n][j]     + bf + xa;
            rb[n * 2 + j] = c2[n][2 + j] + bf + xb;
            suma += ra[n * 2 + j];
            sumb += rb[n * 2 + j];
        }
    }
    suma += __shfl_xor_sync(0xffffffffu, suma, 1);
    suma += __shfl_xor_sync(0xffffffffu, suma, 2);
    sumb += __shfl_xor_sync(0xffffffffu, sumb, 1);
    sumb += __shfl_xor_sync(0xffffffffu, sumb, 2);
    const float ma = suma * (1.f / 64.f);
    const float mb = sumb * (1.f / 64.f);

    float vsa = 0.f, vsb = 0.f;
    #pragma unroll
    for (int i = 0; i < 16; i++) {
        float da = ra[i] - ma; vsa += da * da;
        float db = rb[i] - mb; vsb += db * db;
    }
    vsa += __shfl_xor_sync(0xffffffffu, vsa, 1);
    vsa += __shfl_xor_sync(0xffffffffu, vsa, 2);
    vsb += __shfl_xor_sync(0xffffffffu, vsb, 1);
    vsb += __shfl_xor_sync(0xffffffffu, vsb, 2);
    const float rsa = rsqrtf(vsa * (1.f / 64.f) + EPS_);
    const float rsb = rsqrtf(vsb * (1.f / 64.f) + EPS_);

    #pragma unroll
    for (int n = 0; n < 8; n++) {
        #pragma unroll
        for (int j = 0; j < 2; j++) {
            int col = n * 8 + 2 * t4 + j;
            float gg = g2v[col], bb = b2v[col];
            if (va) out[(size_t)qa * 64 + col] = (ra[n * 2 + j] - ma) * rsa * gg + bb;
            if (vb) out[(size_t)qb * 64 + col] = (rb[n * 2 + j] - mb) * rsb * gg + bb;
        }
    }
}

// ======================================================================
// launcher
// ======================================================================
extern "C" void kernel_launch(void* const* d_in, const int* in_sizes, int n_in,
                              void* d_out, int out_size)
{
    const float* q_feat = (const float*)d_in[0];
    const float* dvf    = (const float*)d_in[1];
    const float* ref    = (const float*)d_in[2];
    const float* q_pos  = (const float*)d_in[3];
    const float* Wv   = (const float*)d_in[6];
    const float* bv   = (const float*)d_in[7];
    const float* Wo   = (const float*)d_in[8];
    const float* bo   = (const float*)d_in[9];
    const float* Wa   = (const float*)d_in[10];
    const float* ba   = (const float*)d_in[11];
    const float* Wout = (const float*)d_in[12];
    const float* bout = (const float*)d_in[13];
    const float* g1   = (const float*)d_in[14];
    const float* b1   = (const float*)d_in[15];
    const float* W1   = (const float*)d_in[16];
    const float* bff1 = (const float*)d_in[17];
    const float* W2   = (const float*)d_in[18];
    const float* bff2 = (const float*)d_in[19];
    const float* g2   = (const float*)d_in[20];
    const float* b2   = (const float*)d_in[21];
    float* out = (float*)d_out;

    float *p_value, *p_off, *p_logits;
    cudaGetSymbolAddress((void**)&p_value,  g_value);
    cudaGetSymbolAddress((void**)&p_off,    g_off);
    cudaGetSymbolAddress((void**)&p_logits, g_logits);

    cudaFuncSetAttribute(ffn_mma_kernel,
                         cudaFuncAttributeMaxDynamicSharedMemorySize, FFN_SMEM_BYTES);

    // 0. transpose + tf32-round FFN weights
    transpose_w_kernel<<<256, 256>>>(W1, W2);
    // 1. value projection
    gemm64_kernel<64><<<dim3((MV_ + 63) / 64, 1), 256>>>(dvf, nullptr, Wv, bv, p_value, MV_);
    // 2. sampling offsets
    gemm64_kernel<320><<<dim3(MQ_ / 64, 5), 256>>>(q_feat, q_pos, Wo, bo, p_off, MQ_);
    // 3. attention logits
    gemm64_kernel<160><<<dim3(MQ_ / 64, 3), 256>>>(q_feat, q_pos, Wa, ba, p_logits, MQ_);
    // 4. softmax + deformable bilinear sampling
    sample_kernel<<<MQ_ / 4, 256>>>(ref);
    // 5. output projection + residual + LN1
    proj_ln1_kernel<<<MQ_ / 8, 256>>>(q_feat, Wout, bout, g1, b1);
    // 6. FFN (mma.sync tf32) + residual + LN2
    ffn_mma_kernel<<<(MQ_ + 127) / 128, 256, FFN_SMEM_BYTES>>>(
        bff1, bff2, g2, b2, out);
}

// round 14
// speedup vs baseline: 2.0977x; 2.0977x over previous
#include <cuda_runtime.h>
#include <cstdint>

// ---------------- problem constants (fixed by setup_inputs) ----------------
#define B_      2
#define NQ_     20000
#define MQ_     (B_*NQ_)          // 40000
#define LIN_    45109
#define MV_     (B_*LIN_)         // 90218
#define DM_     64
#define HEADS_  8
#define DH_     8
#define LEVELS_ 5
#define POINTS_ 4
#define EPS_    1e-5f

__device__ __constant__ int c_W[5] = {184, 92, 46, 23, 12};
__device__ __constant__ int c_H[5] = {184, 92, 46, 23, 12};
__device__ __constant__ int c_S[5] = {0, 33856, 42320, 44436, 44965};

// ---------------- scratch (device globals; no runtime allocation) ----------
__device__ float g_value [(size_t)MV_ * 64];     // 23.1 MB
__device__ float g_off   [(size_t)MQ_ * 320];    // 51.2 MB
__device__ float g_logits[(size_t)MQ_ * 160];    // 25.6 MB
__device__ float g_attn  [(size_t)MQ_ * 64];     // 10.2 MB
__device__ float g_x     [(size_t)MQ_ * 64];     // 10.2 MB
__device__ uint2 g_W1F   [16384];                // W1 bf16 fragment-ordered
__device__ uint2 g_W2F   [16384];                // W2 bf16 fragment-ordered

// ---------------- packed fp32x2 helpers ------------------------------------
typedef unsigned long long u64;

__device__ __forceinline__ void fma2(u64 &d, u64 a, u64 b) {
    asm("fma.rn.f32x2 %0, %1, %2, %0;" : "+l"(d) : "l"(a), "l"(b));
}
__device__ __forceinline__ u64 bcast2(float a) {
    u64 r; asm("mov.b64 %0, {%1, %1};" : "=l"(r) : "f"(a)); return r;
}
__device__ __forceinline__ float2 unpack2(u64 v) {
    float2 f; asm("mov.b64 {%0, %1}, %2;" : "=f"(f.x), "=f"(f.y) : "l"(v)); return f;
}

// pack two fp32 -> bf16x2 (lo = element with smaller k)
__device__ __forceinline__ uint32_t pk_bf16(float lo, float hi) {
    uint32_t d;
    asm("cvt.rn.bf16x2.f32 %0, %1, %2;" : "=r"(d) : "f"(hi), "f"(lo));
    return d;
}

// m16n8k16 bf16 mma (sm_80+ baseline feature; compiles at compute_103)
__device__ __forceinline__ void mma_bf16(float c[4], const uint32_t a[4],
                                         uint32_t b0, uint32_t b1) {
    asm("mma.sync.aligned.m16n8k16.row.col.f32.bf16.bf16.f32 "
        "{%0,%1,%2,%3}, {%4,%5,%6,%7}, {%8,%9}, {%0,%1,%2,%3};"
        : "+f"(c[0]), "+f"(c[1]), "+f"(c[2]), "+f"(c[3])
        : "r"(a[0]), "r"(a[1]), "r"(a[2]), "r"(a[3]), "r"(b0), "r"(b1));
}

// ======================================================================
// Prep: pack W1/W2 into bf16x2 fragment order for m16n8k16 B-operands.
// W1F[((ch*4+s)*16+n)*32+lane] : b0/b1 for GEMM1 (k=in-dim, n=hid)
// W2F[((ch*8+s)*8+n)*32+lane]  : b0/b1 for GEMM2 (k=hid,    n=out)
// ======================================================================
__global__ __launch_bounds__(256)
void prep_wfrag_kernel(const float* __restrict__ W1, const float* __restrict__ W2)
{
    int i = blockIdx.x * 256 + threadIdx.x;
    if (i < 16384) {
        int lane = i & 31, n = (i >> 5) & 15, s = (i >> 9) & 3, ch = i >> 11;
        int col = ch * 128 + n * 8 + (lane >> 2);
        int k0  = s * 16 + 2 * (lane & 3);
        uint2 v;
        v.x = pk_bf16(W1[(size_t)k0 * 1024 + col],       W1[(size_t)(k0 + 1) * 1024 + col]);
        v.y = pk_bf16(W1[(size_t)(k0 + 8) * 1024 + col], W1[(size_t)(k0 + 9) * 1024 + col]);
        g_W1F[i] = v;
    } else {
        int j = i - 16384;
        int lane = j & 31, n = (j >> 5) & 7, s = (j >> 8) & 7, ch = j >> 11;
        int col = n * 8 + (lane >> 2);
        int hid = ch * 128 + s * 16 + 2 * (lane & 3);
        uint2 v;
        v.x = pk_bf16(W2[(size_t)hid * 64 + col],       W2[(size_t)(hid + 1) * 64 + col]);
        v.y = pk_bf16(W2[(size_t)(hid + 8) * 64 + col], W2[(size_t)(hid + 9) * 64 + col]);
        g_W2F[j] = v;
    }
}

// ======================================================================
// Generic K=64 GEMM (fp32 FFMA2) for value/offset/logit projections.
// ======================================================================
template <int N>
__global__ __launch_bounds__(256)
void gemm64_kernel(const float* __restrict__ A1, const float* __restrict__ A2,
                   const float* __restrict__ W,  const float* __restrict__ bias,
                   float* __restrict__ C, int M)
{
    __shared__ float As[64 * 65];
    __shared__ float Ws[64 * 64];

    const int tid = threadIdx.x;
    const int m0  = blockIdx.x * 64;
    const int n0  = blockIdx.y * 64;

    #pragma unroll
    for (int i = 0; i < 4; i++) {
        int f   = tid + 256 * i;
        int row = f >> 4;
        int kc  = (f & 15) * 4;
        float4 v = make_float4(0.f, 0.f, 0.f, 0.f);
        if (m0 + row < M) {
            v = *(const float4*)&A1[(size_t)(m0 + row) * 64 + kc];
            if (A2) {
                float4 u = *(const float4*)&A2[(size_t)(m0 + row) * 64 + kc];
                v.x += u.x; v.y += u.y; v.z += u.z; v.w += u.w;
            }
        }
        As[(kc + 0) * 65 + row] = v.x;
        As[(kc + 1) * 65 + row] = v.y;
        As[(kc + 2) * 65 + row] = v.z;
        As[(kc + 3) * 65 + row] = v.w;
    }
    #pragma unroll
    for (int i = 0; i < 4; i++) {
        int f  = tid + 256 * i;
        int k  = f >> 4;
        int c4 = (f & 15) * 4;
        int col = n0 + c4;
        float4 v = make_float4(0.f, 0.f, 0.f, 0.f);
        if (col + 3 < N) {
            v = *(const float4*)&W[(size_t)k * N + col];
        } else {
            float t[4] = {0.f, 0.f, 0.f, 0.f};
            #pragma unroll
            for (int j = 0; j < 4; j++)
                if (col + j < N) t[j] = W[(size_t)k * N + col + j];
            v = make_float4(t[0], t[1], t[2], t[3]);
        }
        *(float4*)&Ws[k * 64 + c4] = v;
    }
    __syncthreads();

    const int tx = tid & 15;
    const int ty = tid >> 4;

    u64 acc[4][2];
    #pragma unroll
    for (int i = 0; i < 4; i++) { acc[i][0] = 0ull; acc[i][1] = 0ull; }

    #pragma unroll 8
    for (int k = 0; k < 64; k++) {
        ulonglong2 bv = *(const ulonglong2*)&Ws[k * 64 + tx * 4];
        #pragma unroll
        for (int i = 0; i < 4; i++) {
            u64 ap = bcast2(As[k * 65 + ty + 16 * i]);
            fma2(acc[i][0], ap, bv.x);
            fma2(acc[i][1], ap, bv.y);
        }
    }

    #pragma unroll
    for (int i = 0; i < 4; i++) {
        int row = m0 + ty + 16 * i;
        if (row >= M) continue;
        int col = n0 + tx * 4;
        float2 lo = unpack2(acc[i][0]);
        float2 hi = unpack2(acc[i][1]);
        float r[4] = {lo.x, lo.y, hi.x, hi.y};
        #pragma unroll
        for (int j = 0; j < 4; j++)
            if (col + j < N)
                C[(size_t)row * N + col + j] = r[j] + bias[col + j];
    }
}

// ======================================================================
// Deformable sampling: 2 warps per query (16B per lane, paired lanes
// share a 128B line).
// ======================================================================
__global__ __launch_bounds__(256)
void sample_kernel(const float* __restrict__ ref)
{
    const int gw = (blockIdx.x * 256 + threadIdx.x) >> 5;
    const int q  = gw >> 1;
    const int sub  = gw & 1;
    const int lane = threadIdx.x & 31;
    const int idx  = lane >> 1;
    const int half = lane & 1;
    const int h = sub * 4 + (idx >> 2);
    const int p = idx & 3;
    const int b = q / NQ_;

    const float* vb = g_value + (size_t)b * LIN_ * 64;
    const float rx = ref[q * 2 + 0];
    const float ry = ref[q * 2 + 1];

    const float* lg = g_logits + (size_t)q * 160 + h * 20;
    float m = -1e30f;
    #pragma unroll
    for (int i = 0; i < 20; i++) m = fmaxf(m, lg[i]);
    float s = 0.f, w5[5];
    #pragma unroll
    for (int i = 0; i < 20; i++) {
        float e = __expf(lg[i] - m);
        s += e;
        if ((i & 3) == p) w5[i >> 2] = e;
    }
    const float inv = 1.f / s;

    float acc[4] = {0.f, 0.f, 0.f, 0.f};
    const float* offq = g_off + (size_t)q * 320 + (h * 20 + p) * 2;

    #pragma unroll
    for (int l = 0; l < LEVELS_; l++) {
        const int   Wl = c_W[l], Hl = c_H[l], st = c_S[l];
        const float offx = offq[l * 8 + 0];
        const float offy = offq[l * 8 + 1];
        const float x = rx * (float)Wl + offx - 0.5f;
        const float y = ry * (float)Hl + offy - 0.5f;
        const float xf = floorf(x), yf = floorf(y);
        const float wx = x - xf, wy = y - yf;
        const int x0 = (int)xf, y0 = (int)yf;
        const float wt = w5[l] * inv;
        #pragma unroll
        for (int dy = 0; dy < 2; dy++) {
            #pragma unroll
            for (int dx = 0; dx < 2; dx++) {
                const int xc = x0 + dx, yc = y0 + dy;
                if (xc >= 0 && xc < Wl && yc >= 0 && yc < Hl) {
                    const float cw = (dx ? wx : 1.f - wx) * (dy ? wy : 1.f - wy) * wt;
                    const float4 v = *(const float4*)
                        (vb + ((size_t)(st + yc * Wl + xc) * 64 + h * 8 + half * 4));
                    acc[0] += cw * v.x; acc[1] += cw * v.y;
                    acc[2] += cw * v.z; acc[3] += cw * v.w;
                }
            }
        }
    }
    #pragma unroll
    for (int d = 0; d < 4; d++) {
        float v = acc[d];
        v += __shfl_xor_sync(0xffffffffu, v, 2);
        v += __shfl_xor_sync(0xffffffffu, v, 4);
        acc[d] = v;
    }
    if (p == 0) {
        *(float4*)&g_attn[(size_t)q * 64 + h * 8 + half * 4] =
            make_float4(acc[0], acc[1], acc[2], acc[3]);
    }
}

// ======================================================================
// attn_out @ Wout + bout, residual with q_feat, LayerNorm1.  Warp/query.
// ======================================================================
__global__ __launch_bounds__(256)
void proj_ln1_kernel(const float* __restrict__ qfeat,
                     const float* __restrict__ Wout, const float* __restrict__ bout,
                     const float* __restrict__ g1,   const float* __restrict__ b1)
{
    __shared__ float Ws[64 * 64];
    const int tid = threadIdx.x;
    #pragma unroll
    for (int i = tid * 4; i < 4096; i += 1024)
        *(float4*)&Ws[i] = *(const float4*)&Wout[i];
    __syncthreads();

    const int q = blockIdx.x * 8 + (tid >> 5);
    const int lane = tid & 31;

    const float a0 = g_attn[(size_t)q * 64 + lane];
    const float a1 = g_attn[(size_t)q * 64 + lane + 32];
    float acc0 = 0.f, acc1 = 0.f;
    #pragma unroll 8
    for (int k = 0; k < 32; k++) {
        float a = __shfl_sync(0xffffffffu, a0, k);
        acc0 += a * Ws[k * 64 + lane];
        acc1 += a * Ws[k * 64 + lane + 32];
    }
    #pragma unroll 8
    for (int k = 0; k < 32; k++) {
        float a = __shfl_sync(0xffffffffu, a1, k);
        acc0 += a * Ws[(k + 32) * 64 + lane];
        acc1 += a * Ws[(k + 32) * 64 + lane + 32];
    }
    float r0 = qfeat[(size_t)q * 64 + lane]      + acc0 + bout[lane];
    float r1 = qfeat[(size_t)q * 64 + lane + 32] + acc1 + bout[lane + 32];

    float sum = r0 + r1;
    #pragma unroll
    for (int o = 16; o; o >>= 1) sum += __shfl_xor_sync(0xffffffffu, sum, o);
    const float mean = sum * (1.f / 64.f);
    float d0 = r0 - mean, d1 = r1 - mean;
    float vs = d0 * d0 + d1 * d1;
    #pragma unroll
    for (int o = 16; o; o >>= 1) vs += __shfl_xor_sync(0xffffffffu, vs, o);
    const float rs = rsqrtf(vs * (1.f / 64.f) + EPS_);

    g_x[(size_t)q * 64 + lane]      = d0 * rs * g1[lane]      + b1[lane];
    g_x[(size_t)q * 64 + lane + 32] = d1 * rs * g1[lane + 32] + b1[lane + 32];
}

// ======================================================================
// FFN (64 -> 1024 relu -> 64) + residual + LN2 via mma.sync bf16 m16n8k16.
// CTA = 128 queries, 8 warps, each warp one 16-row m-tile.
//  - X A-fragments (bf16x2) live in 16 registers for all 8 chunks
//  - W chunks staged in fragment order (coalesced 32KB copies, ping-pong)
//  - GEMM1 C-frags ARE GEMM2 A-frags: bias+relu+pack entirely in registers
//  - GEMM1 split into two n-halves to keep c1 at 32 regs (2 CTAs/SM)
//  - residual + LN2 fused on register-resident c2 fragments
// ======================================================================
#define FFN_SMEM_BYTES (65536 + 4096)

__global__ __launch_bounds__(256, 2)
void ffn_bf16_kernel(const float* __restrict__ bff1, const float* __restrict__ bff2,
                     const float* __restrict__ g2v,  const float* __restrict__ b2v,
                     float* __restrict__ out)
{
    extern __shared__ __align__(16) char smem[];
    uint2* wbuf0 = (uint2*)smem;             // [0:2048) W1F chunk, [2048:4096) W2F chunk
    uint2* wbuf1 = (uint2*)(smem + 32768);
    float* b1s   = (float*)(smem + 65536);   // 1024 floats
    float* xs    = (float*)smem;             // alias: [128][68] staging (consumed early)

    const int tid  = threadIdx.x;
    const int w    = tid >> 5;
    const int lane = tid & 31;
    const int g    = lane >> 2;
    const int t4   = lane & 3;
    const int q0   = blockIdx.x * 128;

    // ---- stage x + bias1 ----
    #pragma unroll
    for (int it = tid; it < 2048; it += 256) {
        int row = it >> 4, c4 = (it & 15) * 4;
        float4 v = make_float4(0.f, 0.f, 0.f, 0.f);
        if (q0 + row < MQ_) v = *(const float4*)&g_x[(size_t)(q0 + row) * 64 + c4];
        *(float4*)&xs[row * 68 + c4] = v;
    }
    #pragma unroll
    for (int i = tid; i < 1024; i += 256) b1s[i] = bff1[i];
    __syncthreads();

    // ---- X A-fragments -> 16 bf16x2 registers (all 4 k-steps) ----
    uint32_t a[4][4];
    {
        const int r0 = w * 16 + g;
        #pragma unroll
        for (int s = 0; s < 4; s++) {
            int k0 = s * 16 + 2 * t4;
            a[s][0] = pk_bf16(xs[r0 * 68 + k0],           xs[r0 * 68 + k0 + 1]);
            a[s][1] = pk_bf16(xs[(r0 + 8) * 68 + k0],     xs[(r0 + 8) * 68 + k0 + 1]);
            a[s][2] = pk_bf16(xs[r0 * 68 + k0 + 8],       xs[r0 * 68 + k0 + 9]);
            a[s][3] = pk_bf16(xs[(r0 + 8) * 68 + k0 + 8], xs[(r0 + 8) * 68 + k0 + 9]);
        }
    }
    __syncthreads();   // xs dead; weight buffers free

    float c2[8][4];
    #pragma unroll
    for (int n = 0; n < 8; n++)
        #pragma unroll
        for (int j = 0; j < 4; j++) c2[n][j] = 0.f;

    // stage chunk 0
    #pragma unroll
    for (int it = tid; it < 4096; it += 256)
        wbuf0[it] = (it < 2048) ? g_W1F[it] : g_W2F[it - 2048];
    __syncthreads();

    for (int ch = 0; ch < 8; ch++) {
        uint2* cur = (ch & 1) ? wbuf1 : wbuf0;
        uint2* nxt = (ch & 1) ? wbuf0 : wbuf1;
        if (ch < 7) {
            const int base = (ch + 1) * 2048;
            #pragma unroll
            for (int it = tid; it < 4096; it += 256)
                nxt[it] = (it < 2048) ? g_W1F[base + it] : g_W2F[base + it - 2048];
        }

        uint2* w2c = cur + 2048;
        #pragma unroll
        for (int half = 0; half < 2; half++) {
            // GEMM1 half: c1[8] over n = half*8 .. half*8+7
            float c1[8][4];
            #pragma unroll
            for (int n = 0; n < 8; n++)
                #pragma unroll
                for (int j = 0; j < 4; j++) c1[n][j] = 0.f;

            #pragma unroll
            for (int s = 0; s < 4; s++)
                #pragma unroll
                for (int n = 0; n < 8; n++) {
                    uint2 b = cur[(s * 16 + half * 8 + n) * 32 + lane];
                    mma_bf16(c1[n], a[s], b.x, b.y);
                }

            // bias+relu+pack (registers only) then GEMM2 k-steps of this half
            #pragma unroll
            for (int t = 0; t < 4; t++) {
                const int tg = half * 4 + t;
                const int cA = ch * 128 + (half * 8 + 2 * t) * 8 + 2 * t4;
                const int cB = cA + 8;
                const float bA0 = b1s[cA], bA1 = b1s[cA + 1];
                const float bB0 = b1s[cB], bB1 = b1s[cB + 1];
                uint32_t af[4];
                af[0] = pk_bf16(fmaxf(c1[2*t][0]   + bA0, 0.f), fmaxf(c1[2*t][1]   + bA1, 0.f));
                af[1] = pk_bf16(fmaxf(c1[2*t][2]   + bA0, 0.f), fmaxf(c1[2*t][3]   + bA1, 0.f));
                af[2] = pk_bf16(fmaxf(c1[2*t+1][0] + bB0, 0.f), fmaxf(c1[2*t+1][1] + bB1, 0.f));
                af[3] = pk_bf16(fmaxf(c1[2*t+1][2] + bB0, 0.f), fmaxf(c1[2*t+1][3] + bB1, 0.f));
                #pragma unroll
                for (int n = 0; n < 8; n++) {
                    uint2 b = w2c[(tg * 8 + n) * 32 + lane];
                    mma_bf16(c2[n], af, b.x, b.y);
                }
            }
        }
        __syncthreads();
    }

    // ---- epilogue: residual + LN2 on c2 fragments ----
    const int qa = q0 + w * 16 + g;
    const int qb = qa + 8;
    const bool va = qa < MQ_, vb = qb < MQ_;

    float ra[16], rb[16];
    float suma = 0.f, sumb = 0.f;
    #pragma unroll
    for (int n = 0; n < 8; n++) {
        #pragma unroll
        for (int j = 0; j < 2; j++) {
            int col = n * 8 + 2 * t4 + j;
            float bf = bff2[col];
            float xa = va ? g_x[(size_t)qa * 64 + col] : 0.f;
            float xb = vb ? g_x[(size_t)qb * 64 + col] : 0.f;
            ra[n * 2 + j] = c2[n][j]     + bf + xa;
            rb[n * 2 + j] = c2[n][2 + j] + bf + xb;
            suma += ra[n * 2 + j];
            sumb += rb[n * 2 + j];
        }
    }
    suma += __shfl_xor_sync(0xffffffffu, suma, 1);
    suma += __shfl_xor_sync(0xffffffffu, suma, 2);
    sumb += __shfl_xor_sync(0xffffffffu, sumb, 1);
    sumb += __shfl_xor_sync(0xffffffffu, sumb, 2);
    const float ma = suma * (1.f / 64.f);
    const float mb = sumb * (1.f / 64.f);

    float vsa = 0.f, vsb = 0.f;
    #pragma unroll
    for (int i = 0; i < 16; i++) {
        float da = ra[i] - ma; vsa += da * da;
        float db = rb[i] - mb; vsb += db * db;
    }
    vsa += __shfl_xor_sync(0xffffffffu, vsa, 1);
    vsa += __shfl_xor_sync(0xffffffffu, vsa, 2);
    vsb += __shfl_xor_sync(0xffffffffu, vsb, 1);
    vsb += __shfl_xor_sync(0xffffffffu, vsb, 2);
    const float rsa = rsqrtf(vsa * (1.f / 64.f) + EPS_);
    const float rsb = rsqrtf(vsb * (1.f / 64.f) + EPS_);

    #pragma unroll
    for (int n = 0; n < 8; n++) {
        #pragma unroll
        for (int j = 0; j < 2; j++) {
            int col = n * 8 + 2 * t4 + j;
            float gg = g2v[col], bb = b2v[col];
            if (va) out[(size_t)qa * 64 + col] = (ra[n * 2 + j] - ma) * rsa * gg + bb;
            if (vb) out[(size_t)qb * 64 + col] = (rb[n * 2 + j] - mb) * rsb * gg + bb;
        }
    }
}

// ======================================================================
// launcher
// ======================================================================
extern "C" void kernel_launch(void* const* d_in, const int* in_sizes, int n_in,
                              void* d_out, int out_size)
{
    const float* q_feat = (const float*)d_in[0];
    const float* dvf    = (const float*)d_in[1];
    const float* ref    = (const float*)d_in[2];
    const float* q_pos  = (const float*)d_in[3];
    const float* Wv   = (const float*)d_in[6];
    const float* bv   = (const float*)d_in[7];
    const float* Wo   = (const float*)d_in[8];
    const float* bo   = (const float*)d_in[9];
    const float* Wa   = (const float*)d_in[10];
    const float* ba   = (const float*)d_in[11];
    const float* Wout = (const float*)d_in[12];
    const float* bout = (const float*)d_in[13];
    const float* g1   = (const float*)d_in[14];
    const float* b1   = (const float*)d_in[15];
    const float* W1   = (const float*)d_in[16];
    const float* bff1 = (const float*)d_in[17];
    const float* W2   = (const float*)d_in[18];
    const float* bff2 = (const float*)d_in[19];
    const float* g2   = (const float*)d_in[20];
    const float* b2   = (const float*)d_in[21];
    float* out = (float*)d_out;

    float *p_value, *p_off, *p_logits;
    cudaGetSymbolAddress((void**)&p_value,  g_value);
    cudaGetSymbolAddress((void**)&p_off,    g_off);
    cudaGetSymbolAddress((void**)&p_logits, g_logits);

    cudaFuncSetAttribute(ffn_bf16_kernel,
                         cudaFuncAttributeMaxDynamicSharedMemorySize, FFN_SMEM_BYTES);

    // 0. pack FFN weights into bf16 fragment order
    prep_wfrag_kernel<<<128, 256>>>(W1, W2);
    // 1. value projection
    gemm64_kernel<64><<<dim3((MV_ + 63) / 64, 1), 256>>>(dvf, nullptr, Wv, bv, p_value, MV_);
    // 2. sampling offsets
    gemm64_kernel<320><<<dim3(MQ_ / 64, 5), 256>>>(q_feat, q_pos, Wo, bo, p_off, MQ_);
    // 3. attention logits
    gemm64_kernel<160><<<dim3(MQ_ / 64, 3), 256>>>(q_feat, q_pos, Wa, ba, p_logits, MQ_);
    // 4. softmax + deformable bilinear sampling
    sample_kernel<<<MQ_ / 4, 256>>>(ref);
    // 5. output projection + residual + LN1
    proj_ln1_kernel<<<MQ_ / 8, 256>>>(q_feat, Wout, bout, g1, b1);
    // 6. FFN (mma.sync bf16) + residual + LN2
    ffn_bf16_kernel<<<(MQ_ + 127) / 128, 256, FFN_SMEM_BYTES>>>(
        bff1, bff2, g2, b2, out);
}

// round 17
// speedup vs baseline: 2.9336x; 1.3985x over previous
#include <cuda_runtime.h>
#include <cstdint>

// ---------------- problem constants (fixed by setup_inputs) ----------------
#define B_      2
#define NQ_     20000
#define MQ_     (B_*NQ_)          // 40000
#define LIN_    45109
#define MV_     (B_*LIN_)         // 90218
#define DM_     64
#define HEADS_  8
#define DH_     8
#define LEVELS_ 5
#define POINTS_ 4
#define EPS_    1e-5f

__device__ __constant__ int c_W[5] = {184, 92, 46, 23, 12};
__device__ __constant__ int c_H[5] = {184, 92, 46, 23, 12};
__device__ __constant__ int c_S[5] = {0, 33856, 42320, 44436, 44965};

// ---------------- scratch (device globals; no runtime allocation) ----------
__device__ float g_value [(size_t)MV_ * 64];     // 23.1 MB
__device__ float g_off   [(size_t)MQ_ * 320];    // 51.2 MB
__device__ float g_logits[(size_t)MQ_ * 160];    // 25.6 MB
__device__ float g_attn  [(size_t)MQ_ * 64];     // 10.2 MB
__device__ float g_x     [(size_t)MQ_ * 64];     // 10.2 MB
__device__ uint2 g_W1F   [16384];                // W1 bf16 fragment-ordered (FFN)
__device__ uint2 g_W2F   [16384];                // W2 bf16 fragment-ordered (FFN)
__device__ uint2 g_WQF   [7680];                 // [Wo | Wa] fragment-ordered, 60 tiles
__device__ uint2 g_WVF   [1024];                 // Wv fragment-ordered, 8 tiles
__device__ uint2 g_WOF   [1024];                 // Wout fragment-ordered, 8 tiles

// ---------------- bf16 mma helpers -----------------------------------------
__device__ __forceinline__ uint32_t pk_bf16(float lo, float hi) {
    uint32_t d;
    asm("cvt.rn.bf16x2.f32 %0, %1, %2;" : "=r"(d) : "f"(hi), "f"(lo));
    return d;
}

// m16n8k16 bf16 mma (sm_80+ baseline; compiles at compute_103)
__device__ __forceinline__ void mma_bf16(float c[4], const uint32_t a[4],
                                         uint32_t b0, uint32_t b1) {
    asm("mma.sync.aligned.m16n8k16.row.col.f32.bf16.bf16.f32 "
        "{%0,%1,%2,%3}, {%4,%5,%6,%7}, {%8,%9}, {%0,%1,%2,%3};"
        : "+f"(c[0]), "+f"(c[1]), "+f"(c[2]), "+f"(c[3])
        : "r"(a[0]), "r"(a[1]), "r"(a[2]), "r"(a[3]), "r"(b0), "r"(b1));
}

// ======================================================================
// Prep A: W1/W2 -> bf16 fragment order (FFN).
// ======================================================================
__global__ __launch_bounds__(256)
void prep_wfrag_kernel(const float* __restrict__ W1, const float* __restrict__ W2)
{
    int i = blockIdx.x * 256 + threadIdx.x;
    if (i < 16384) {
        int lane = i & 31, n = (i >> 5) & 15, s = (i >> 9) & 3, ch = i >> 11;
        int col = ch * 128 + n * 8 + (lane >> 2);
        int k0  = s * 16 + 2 * (lane & 3);
        uint2 v;
        v.x = pk_bf16(W1[(size_t)k0 * 1024 + col],       W1[(size_t)(k0 + 1) * 1024 + col]);
        v.y = pk_bf16(W1[(size_t)(k0 + 8) * 1024 + col], W1[(size_t)(k0 + 9) * 1024 + col]);
        g_W1F[i] = v;
    } else {
        int j = i - 16384;
        int lane = j & 31, n = (j >> 5) & 7, s = (j >> 8) & 7, ch = j >> 11;
        int col = n * 8 + (lane >> 2);
        int hid = ch * 128 + s * 16 + 2 * (lane & 3);
        uint2 v;
        v.x = pk_bf16(W2[(size_t)hid * 64 + col],       W2[(size_t)(hid + 1) * 64 + col]);
        v.y = pk_bf16(W2[(size_t)(hid + 8) * 64 + col], W2[(size_t)(hid + 9) * 64 + col]);
        g_W2F[j] = v;
    }
}

// ======================================================================
// Prep B: Wo/Wa (fused, 60 tiles) + Wv + Wout -> bf16 fragment order.
// Buffer layout: frag[(nt*4+s)*32+lane] ; 9728 items total.
// ======================================================================
__global__ __launch_bounds__(256)
void prep_wproj_kernel(const float* __restrict__ Wo, const float* __restrict__ Wa,
                       const float* __restrict__ Wv, const float* __restrict__ Wout)
{
    int i = blockIdx.x * 256 + threadIdx.x;
    if (i < 7680) {
        int lane = i & 31, s = (i >> 5) & 3, nt = i >> 7;
        int k0 = s * 16 + 2 * (lane & 3);
        uint2 v;
        if (nt < 40) {
            int col = nt * 8 + (lane >> 2);
            v.x = pk_bf16(Wo[(size_t)k0 * 320 + col],       Wo[(size_t)(k0 + 1) * 320 + col]);
            v.y = pk_bf16(Wo[(size_t)(k0 + 8) * 320 + col], Wo[(size_t)(k0 + 9) * 320 + col]);
        } else {
            int col = (nt - 40) * 8 + (lane >> 2);
            v.x = pk_bf16(Wa[(size_t)k0 * 160 + col],       Wa[(size_t)(k0 + 1) * 160 + col]);
            v.y = pk_bf16(Wa[(size_t)(k0 + 8) * 160 + col], Wa[(size_t)(k0 + 9) * 160 + col]);
        }
        g_WQF[i] = v;
    } else if (i < 8704) {
        int j = i - 7680;
        int lane = j & 31, s = (j >> 5) & 3, nt = j >> 7;
        int col = nt * 8 + (lane >> 2);
        int k0  = s * 16 + 2 * (lane & 3);
        uint2 v;
        v.x = pk_bf16(Wv[(size_t)k0 * 64 + col],       Wv[(size_t)(k0 + 1) * 64 + col]);
        v.y = pk_bf16(Wv[(size_t)(k0 + 8) * 64 + col], Wv[(size_t)(k0 + 9) * 64 + col]);
        g_WVF[j] = v;
    } else if (i < 9728) {
        int j = i - 8704;
        int lane = j & 31, s = (j >> 5) & 3, nt = j >> 7;
        int col = nt * 8 + (lane >> 2);
        int k0  = s * 16 + 2 * (lane & 3);
        uint2 v;
        v.x = pk_bf16(Wout[(size_t)k0 * 64 + col],       Wout[(size_t)(k0 + 1) * 64 + col]);
        v.y = pk_bf16(Wout[(size_t)(k0 + 8) * 64 + col], Wout[(size_t)(k0 + 9) * 64 + col]);
        g_WOF[j] = v;
    }
}

// ---------------- shared A-staging + fragment build ------------------------
// Stages 128 rows x 64 cols of (A1 (+A2)) into xs[row*68+col], then builds
// this warp's m16n8k16 A-fragments for all 4 k-steps.
__device__ __forceinline__ void stage_and_frag(
    const float* __restrict__ A1, const float* __restrict__ A2,
    float* xs, uint32_t a[4][4], int q0, int M,
    int tid, int w, int g, int t4)
{
    #pragma unroll
    for (int it = tid; it < 2048; it += 256) {
        int row = it >> 4, c4 = (it & 15) * 4;
        float4 v = make_float4(0.f, 0.f, 0.f, 0.f);
        if (q0 + row < M) {
            v = *(const float4*)&A1[(size_t)(q0 + row) * 64 + c4];
            if (A2) {
                float4 u = *(const float4*)&A2[(size_t)(q0 + row) * 64 + c4];
                v.x += u.x; v.y += u.y; v.z += u.z; v.w += u.w;
            }
        }
        *(float4*)&xs[row * 68 + c4] = v;
    }
    __syncthreads();
    const int r0 = w * 16 + g;
    #pragma unroll
    for (int s = 0; s < 4; s++) {
        int k0 = s * 16 + 2 * t4;
        a[s][0] = pk_bf16(xs[r0 * 68 + k0],           xs[r0 * 68 + k0 + 1]);
        a[s][1] = pk_bf16(xs[(r0 + 8) * 68 + k0],     xs[(r0 + 8) * 68 + k0 + 1]);
        a[s][2] = pk_bf16(xs[r0 * 68 + k0 + 8],       xs[r0 * 68 + k0 + 9]);
        a[s][3] = pk_bf16(xs[(r0 + 8) * 68 + k0 + 8], xs[(r0 + 8) * 68 + k0 + 9]);
    }
}

// ======================================================================
// Value projection: g_value[MV,64] = dvf @ Wv + bv   (bf16 mma)
// ======================================================================
__global__ __launch_bounds__(256)
void vproj_mma_kernel(const float* __restrict__ dvf, const float* __restrict__ bv)
{
    __shared__ float xs[128 * 68];
    const int tid = threadIdx.x;
    const int w = tid >> 5, lane = tid & 31;
    const int g = lane >> 2, t4 = lane & 3;
    const int q0 = blockIdx.x * 128;

    uint32_t a[4][4];
    stage_and_frag(dvf, nullptr, xs, a, q0, MV_, tid, w, g, t4);

    const int r0 = q0 + w * 16 + g;
    #pragma unroll
    for (int nt = 0; nt < 8; nt++) {
        float c[4] = {0.f, 0.f, 0.f, 0.f};
        #pragma unroll
        for (int s = 0; s < 4; s++) {
            uint2 b = g_WQF[0], bb;   // dummy init avoided below
            bb = g_WVF[(nt * 4 + s) * 32 + lane];
            (void)b;
            mma_bf16(c, a[s], bb.x, bb.y);
        }
        const int col = nt * 8 + 2 * t4;
        const float b0 = bv[col], b1 = bv[col + 1];
        if (r0 < MV_)
            *(float2*)&g_value[(size_t)r0 * 64 + col] = make_float2(c[0] + b0, c[1] + b1);
        if (r0 + 8 < MV_)
            *(float2*)&g_value[(size_t)(r0 + 8) * 64 + col] = make_float2(c[2] + b0, c[3] + b1);
    }
}

// ======================================================================
// Fused q-projection: offsets (N=320, tiles 0..39) + logits (N=160,
// tiles 40..59) = (q_feat+q_pos) @ [Wo|Wa] + [bo|ba]   (bf16 mma)
// ======================================================================
__global__ __launch_bounds__(256)
void qproj_mma_kernel(const float* __restrict__ q_feat, const float* __restrict__ q_pos,
                      const float* __restrict__ bo,     const float* __restrict__ ba)
{
    __shared__ float xs[128 * 68];
    const int tid = threadIdx.x;
    const int w = tid >> 5, lane = tid & 31;
    const int g = lane >> 2, t4 = lane & 3;
    const int q0 = blockIdx.x * 128;

    uint32_t a[4][4];
    stage_and_frag(q_feat, q_pos, xs, a, q0, MQ_, tid, w, g, t4);

    const int r0 = q0 + w * 16 + g;
    const bool va = r0 < MQ_, vb = (r0 + 8) < MQ_;

    #pragma unroll 4
    for (int nt = 0; nt < 60; nt++) {
        float c[4] = {0.f, 0.f, 0.f, 0.f};
        #pragma unroll
        for (int s = 0; s < 4; s++) {
            uint2 b = g_WQF[(nt * 4 + s) * 32 + lane];
            mma_bf16(c, a[s], b.x, b.y);
        }
        float* outp; const float* bptr; int rs;
        if (nt < 40) {
            outp = &g_off[(size_t)r0 * 320 + nt * 8 + 2 * t4];
            bptr = &bo[nt * 8 + 2 * t4];
            rs = 320;
        } else {
            outp = &g_logits[(size_t)r0 * 160 + (nt - 40) * 8 + 2 * t4];
            bptr = &ba[(nt - 40) * 8 + 2 * t4];
            rs = 160;
        }
        const float b0 = bptr[0], b1 = bptr[1];
        if (va) *(float2*)outp            = make_float2(c[0] + b0, c[1] + b1);
        if (vb) *(float2*)(outp + 8 * rs) = make_float2(c[2] + b0, c[3] + b1);
    }
}

// ======================================================================
// Deformable sampling: 2 warps per query (16B per lane, paired lanes
// share a 128B line).
// ======================================================================
__global__ __launch_bounds__(256)
void sample_kernel(const float* __restrict__ ref)
{
    const int gw = (blockIdx.x * 256 + threadIdx.x) >> 5;
    const int q  = gw >> 1;
    const int sub  = gw & 1;
    const int lane = threadIdx.x & 31;
    const int idx  = lane >> 1;
    const int half = lane & 1;
    const int h = sub * 4 + (idx >> 2);
    const int p = idx & 3;
    const int b = q / NQ_;

    const float* vb = g_value + (size_t)b * LIN_ * 64;
    const float rx = ref[q * 2 + 0];
    const float ry = ref[q * 2 + 1];

    const float* lg = g_logits + (size_t)q * 160 + h * 20;
    float m = -1e30f;
    #pragma unroll
    for (int i = 0; i < 20; i++) m = fmaxf(m, lg[i]);
    float s = 0.f, w5[5];
    #pragma unroll
    for (int i = 0; i < 20; i++) {
        float e = __expf(lg[i] - m);
        s += e;
        if ((i & 3) == p) w5[i >> 2] = e;
    }
    const float inv = 1.f / s;

    float acc[4] = {0.f, 0.f, 0.f, 0.f};
    const float* offq = g_off + (size_t)q * 320 + (h * 20 + p) * 2;

    #pragma unroll
    for (int l = 0; l < LEVELS_; l++) {
        const int   Wl = c_W[l], Hl = c_H[l], st = c_S[l];
        const float offx = offq[l * 8 + 0];
        const float offy = offq[l * 8 + 1];
        const float x = rx * (float)Wl + offx - 0.5f;
        const float y = ry * (float)Hl + offy - 0.5f;
        const float xf = floorf(x), yf = floorf(y);
        const float wx = x - xf, wy = y - yf;
        const int x0 = (int)xf, y0 = (int)yf;
        const float wt = w5[l] * inv;
        #pragma unroll
        for (int dy = 0; dy < 2; dy++) {
            #pragma unroll
            for (int dx = 0; dx < 2; dx++) {
                const int xc = x0 + dx, yc = y0 + dy;
                if (xc >= 0 && xc < Wl && yc >= 0 && yc < Hl) {
                    const float cw = (dx ? wx : 1.f - wx) * (dy ? wy : 1.f - wy) * wt;
                    const float4 v = *(const float4*)
                        (vb + ((size_t)(st + yc * Wl + xc) * 64 + h * 8 + half * 4));
                    acc[0] += cw * v.x; acc[1] += cw * v.y;
                    acc[2] += cw * v.z; acc[3] += cw * v.w;
                }
            }
        }
    }
    #pragma unroll
    for (int d = 0; d < 4; d++) {
        float v = acc[d];
        v += __shfl_xor_sync(0xffffffffu, v, 2);
        v += __shfl_xor_sync(0xffffffffu, v, 4);
        acc[d] = v;
    }
    if (p == 0) {
        *(float4*)&g_attn[(size_t)q * 64 + h * 8 + half * 4] =
            make_float4(acc[0], acc[1], acc[2], acc[3]);
    }
}

// ======================================================================
// Output projection + residual + LN1 (bf16 mma):
//   g_x = LN1(q_feat + g_attn @ Wout + bout)
// ======================================================================
__global__ __launch_bounds__(256)
void oproj_ln1_mma_kernel(const float* __restrict__ qfeat, const float* __restrict__ bout,
                          const float* __restrict__ g1v,   const float* __restrict__ b1v)
{
    __shared__ float xs[128 * 68];
    const int tid = threadIdx.x;
    const int w = tid >> 5, lane = tid & 31;
    const int g = lane >> 2, t4 = lane & 3;
    const int q0 = blockIdx.x * 128;

    uint32_t a[4][4];
    stage_and_frag(g_attn, nullptr, xs, a, q0, MQ_, tid, w, g, t4);

    float c2[8][4];
    #pragma unroll
    for (int n = 0; n < 8; n++)
        #pragma unroll
        for (int j = 0; j < 4; j++) c2[n][j] = 0.f;

    #pragma unroll
    for (int nt = 0; nt < 8; nt++)
        #pragma unroll
        for (int s = 0; s < 4; s++) {
            uint2 b = g_WOF[(nt * 4 + s) * 32 + lane];
            mma_bf16(c2[nt], a[s], b.x, b.y);
        }

    // residual + LN1 on fragments (t4-group shuffles cover the 64 cols)
    const int qa = q0 + w * 16 + g;
    const int qb = qa + 8;
    const bool va = qa < MQ_, vb = qb < MQ_;

    float ra[16], rb[16];
    float suma = 0.f, sumb = 0.f;
    #pragma unroll
    for (int n = 0; n < 8; n++) {
        #pragma unroll
        for (int j = 0; j < 2; j++) {
            int col = n * 8 + 2 * t4 + j;
            float bf = bout[col];
            float xa = va ? qfeat[(size_t)qa * 64 + col] : 0.f;
            float xb = vb ? qfeat[(size_t)qb * 64 + col] : 0.f;
            ra[n * 2 + j] = c2[n][j]     + bf + xa;
            rb[n * 2 + j] = c2[n][2 + j] + bf + xb;
            suma += ra[n * 2 + j];
            sumb += rb[n * 2 + j];
        }
    }
    suma += __shfl_xor_sync(0xffffffffu, suma, 1);
    suma += __shfl_xor_sync(0xffffffffu, suma, 2);
    sumb += __shfl_xor_sync(0xffffffffu, sumb, 1);
    sumb += __shfl_xor_sync(0xffffffffu, sumb, 2);
    const float ma = suma * (1.f / 64.f);
    const float mb = sumb * (1.f / 64.f);

    float vsa = 0.f, vsb = 0.f;
    #pragma unroll
    for (int i = 0; i < 16; i++) {
        float da = ra[i] - ma; vsa += da * da;
        float db = rb[i] - mb; vsb += db * db;
    }
    vsa += __shfl_xor_sync(0xffffffffu, vsa, 1);
    vsa += __shfl_xor_sync(0xffffffffu, vsa, 2);
    vsb += __shfl_xor_sync(0xffffffffu, vsb, 1);
    vsb += __shfl_xor_sync(0xffffffffu, vsb, 2);
    const float rsa = rsqrtf(vsa * (1.f / 64.f) + EPS_);
    const float rsb = rsqrtf(vsb * (1.f / 64.f) + EPS_);

    #pragma unroll
    for (int n = 0; n < 8; n++) {
        #pragma unroll
        for (int j = 0; j < 2; j++) {
            int col = n * 8 + 2 * t4 + j;
            float gg = g1v[col], bb = b1v[col];
            if (va) g_x[(size_t)qa * 64 + col] = (ra[n * 2 + j] - ma) * rsa * gg + bb;
            if (vb) g_x[(size_t)qb * 64 + col] = (rb[n * 2 + j] - mb) * rsb * gg + bb;
        }
    }
}

// ======================================================================
// FFN (64 -> 1024 relu -> 64) + residual + LN2 via mma.sync bf16 m16n8k16.
// (unchanged from round 12/14 — validated)
// ======================================================================
#define FFN_SMEM_BYTES (65536 + 4096)

__global__ __launch_bounds__(256, 2)
void ffn_bf16_kernel(const float* __restrict__ bff1, const float* __restrict__ bff2,
                     const float* __restrict__ g2v,  const float* __restrict__ b2v,
                     float* __restrict__ out)
{
    extern __shared__ __align__(16) char smem[];
    uint2* wbuf0 = (uint2*)smem;
    uint2* wbuf1 = (uint2*)(smem + 32768);
    float* b1s   = (float*)(smem + 65536);
    float* xs    = (float*)smem;

    const int tid  = threadIdx.x;
    const int w    = tid >> 5;
    const int lane = tid & 31;
    const int g    = lane >> 2;
    const int t4   = lane & 3;
    const int q0   = blockIdx.x * 128;

    #pragma unroll
    for (int it = tid; it < 2048; it += 256) {
        int row = it >> 4, c4 = (it & 15) * 4;
        float4 v = make_float4(0.f, 0.f, 0.f, 0.f);
        if (q0 + row < MQ_) v = *(const float4*)&g_x[(size_t)(q0 + row) * 64 + c4];
        *(float4*)&xs[row * 68 + c4] = v;
    }
    #pragma unroll
    for (int i = tid; i < 1024; i += 256) b1s[i] = bff1[i];
    __syncthreads();

    uint32_t a[4][4];
    {
        const int r0 = w * 16 + g;
        #pragma unroll
        for (int s = 0; s < 4; s++) {
            int k0 = s * 16 + 2 * t4;
            a[s][0] = pk_bf16(xs[r0 * 68 + k0],           xs[r0 * 68 + k0 + 1]);
            a[s][1] = pk_bf16(xs[(r0 + 8) * 68 + k0],     xs[(r0 + 8) * 68 + k0 + 1]);
            a[s][2] = pk_bf16(xs[r0 * 68 + k0 + 8],       xs[r0 * 68 + k0 + 9]);
            a[s][3] = pk_bf16(xs[(r0 + 8) * 68 + k0 + 8], xs[(r0 + 8) * 68 + k0 + 9]);
        }
    }
    __syncthreads();

    float c2[8][4];
    #pragma unroll
    for (int n = 0; n < 8; n++)
        #pragma unroll
        for (int j = 0; j < 4; j++) c2[n][j] = 0.f;

    #pragma unroll
    for (int it = tid; it < 4096; it += 256)
        wbuf0[it] = (it < 2048) ? g_W1F[it] : g_W2F[it - 2048];
    __syncthreads();

    for (int ch = 0; ch < 8; ch++) {
        uint2* cur = (ch & 1) ? wbuf1 : wbuf0;
        uint2* nxt = (ch & 1) ? wbuf0 : wbuf1;
        if (ch < 7) {
            const int base = (ch + 1) * 2048;
            #pragma unroll
            for (int it = tid; it < 4096; it += 256)
                nxt[it] = (it < 2048) ? g_W1F[base + it] : g_W2F[base + it - 2048];
        }

        uint2* w2c = cur + 2048;
        #pragma unroll
        for (int half = 0; half < 2; half++) {
            float c1[8][4];
            #pragma unroll
            for (int n = 0; n < 8; n++)
                #pragma unroll
                for (int j = 0; j < 4; j++) c1[n][j] = 0.f;

            #pragma unroll
            for (int s = 0; s < 4; s++)
                #pragma unroll
                for (int n = 0; n < 8; n++) {
                    uint2 b = cur[(s * 16 + half * 8 + n) * 32 + lane];
                    mma_bf16(c1[n], a[s], b.x, b.y);
                }

            #pragma unroll
            for (int t = 0; t < 4; t++) {
                const int tg = half * 4 + t;
                const int cA = ch * 128 + (half * 8 + 2 * t) * 8 + 2 * t4;
                const int cB = cA + 8;
                const float bA0 = b1s[cA], bA1 = b1s[cA + 1];
                const float bB0 = b1s[cB], bB1 = b1s[cB + 1];
                uint32_t af[4];
                af[0] = pk_bf16(fmaxf(c1[2*t][0]   + bA0, 0.f), fmaxf(c1[2*t][1]   + bA1, 0.f));
                af[1] = pk_bf16(fmaxf(c1[2*t][2]   + bA0, 0.f), fmaxf(c1[2*t][3]   + bA1, 0.f));
                af[2] = pk_bf16(fmaxf(c1[2*t+1][0] + bB0, 0.f), fmaxf(c1[2*t+1][1] + bB1, 0.f));
                af[3] = pk_bf16(fmaxf(c1[2*t+1][2] + bB0, 0.f), fmaxf(c1[2*t+1][3] + bB1, 0.f));
                #pragma unroll
                for (int n = 0; n < 8; n++) {
                    uint2 b = w2c[(tg * 8 + n) * 32 + lane];
                    mma_bf16(c2[n], af, b.x, b.y);
                }
            }
        }
        __syncthreads();
    }

    const int qa = q0 + w * 16 + g;
    const int qb = qa + 8;
    const bool va = qa < MQ_, vb = qb < MQ_;

    float ra[16], rb[16];
    float suma = 0.f, sumb = 0.f;
    #pragma unroll
    for (int n = 0; n < 8; n++) {
        #pragma unroll
        for (int j = 0; j < 2; j++) {
            int col = n * 8 + 2 * t4 + j;
            float bf = bff2[col];
            float xa = va ? g_x[(size_t)qa * 64 + col] : 0.f;
            float xb = vb ? g_x[(size_t)qb * 64 + col] : 0.f;
            ra[n * 2 + j] = c2[n][j]     + bf + xa;
            rb[n * 2 + j] = c2[n][2 + j] + bf + xb;
            suma += ra[n * 2 + j];
            sumb += rb[n * 2 + j];
        }
    }
    suma += __shfl_xor_sync(0xffffffffu, suma, 1);
    suma += __shfl_xor_sync(0xffffffffu, suma, 2);
    sumb += __shfl_xor_sync(0xffffffffu, sumb, 1);
    sumb += __shfl_xor_sync(0xffffffffu, sumb, 2);
    const float ma = suma * (1.f / 64.f);
    const float mb = sumb * (1.f / 64.f);

    float vsa = 0.f, vsb = 0.f;
    #pragma unroll
    for (int i = 0; i < 16; i++) {
        float da = ra[i] - ma; vsa += da * da;
        float db = rb[i] - mb; vsb += db * db;
    }
    vsa += __shfl_xor_sync(0xffffffffu, vsa, 1);
    vsa += __shfl_xor_sync(0xffffffffu, vsa, 2);
    vsb += __shfl_xor_sync(0xffffffffu, vsb, 1);
    vsb += __shfl_xor_sync(0xffffffffu, vsb, 2);
    const float rsa = rsqrtf(vsa * (1.f / 64.f) + EPS_);
    const float rsb = rsqrtf(vsb * (1.f / 64.f) + EPS_);

    #pragma unroll
    for (int n = 0; n < 8; n++) {
        #pragma unroll
        for (int j = 0; j < 2; j++) {
            int col = n * 8 + 2 * t4 + j;
            float gg = g2v[col], bb = b2v[col];
            if (va) out[(size_t)qa * 64 + col] = (ra[n * 2 + j] - ma) * rsa * gg + bb;
            if (vb) out[(size_t)qb * 64 + col] = (rb[n * 2 + j] - mb) * rsb * gg + bb;
        }
    }
}

// ======================================================================
// launcher
// ======================================================================
extern "C" void kernel_launch(void* const* d_in, const int* in_sizes, int n_in,
                              void* d_out, int out_size)
{
    const float* q_feat = (const float*)d_in[0];
    const float* dvf    = (const float*)d_in[1];
    const float* ref    = (const float*)d_in[2];
    const float* q_pos  = (const float*)d_in[3];
    const float* Wv   = (const float*)d_in[6];
    const float* bv   = (const float*)d_in[7];
    const float* Wo   = (const float*)d_in[8];
    const float* bo   = (const float*)d_in[9];
    const float* Wa   = (const float*)d_in[10];
    const float* ba   = (const float*)d_in[11];
    const float* Wout = (const float*)d_in[12];
    const float* bout = (const float*)d_in[13];
    const float* g1   = (const float*)d_in[14];
    const float* b1   = (const float*)d_in[15];
    const float* W1   = (const float*)d_in[16];
    const float* bff1 = (const float*)d_in[17];
    const float* W2   = (const float*)d_in[18];
    const float* bff2 = (const float*)d_in[19];
    const float* g2   = (const float*)d_in[20];
    const float* b2   = (const float*)d_in[21];
    float* out = (float*)d_out;

    cudaFuncSetAttribute(ffn_bf16_kernel,
                         cudaFuncAttributeMaxDynamicSharedMemorySize, FFN_SMEM_BYTES);

    // 0. weight packing (fragment order, bf16)
    prep_wfrag_kernel<<<128, 256>>>(W1, W2);
    prep_wproj_kernel<<<38, 256>>>(Wo, Wa, Wv, Wout);
    // 1. value projection (bf16 mma)
    vproj_mma_kernel<<<(MV_ + 127) / 128, 256>>>(dvf, bv);
    // 2+3. fused sampling-offset + attention-logit projection (bf16 mma)
    qproj_mma_kernel<<<(MQ_ + 127) / 128, 256>>>(q_feat, q_pos, bo, ba);
    // 4. softmax + deformable bilinear sampling
    sample_kernel<<<MQ_ / 4, 256>>>(ref);
    // 5. output projection + residual + LN1 (bf16 mma)
    oproj_ln1_mma_kernel<<<(MQ_ + 127) / 128, 256>>>(q_feat, bout, g1, b1);
    // 6. FFN (mma.sync bf16) + residual + LN2
    ffn_bf16_kernel<<<(MQ_ + 127) / 128, 256, FFN_SMEM_BYTES>>>(
        bff1, bff2, g2, b2, out);
}